// round 5
// baseline (speedup 1.0000x reference)
#include <cuda_runtime.h>
#include <math.h>

#define BB 8
#define NN 2048
#define FIN 256
#define FO 64
#define ALPHA 0.2f

// ---- scratch (allocation-free rule: __device__ globals) ----
__device__ float g_Wh[BB * NN * FO];     // 4 MB
__device__ float g_s1[BB * NN];
__device__ float g_s2[BB * NN];
__device__ float g_s2max[BB];

// ============================================================
// Kernel A: Wh = h @ W^T  (and s1 = Wh.a1, s2 = Wh.a2 fused)
// grid 256 blocks x 64 rows, 128 threads, thread-tile 4r x 8o
// ============================================================
__global__ __launch_bounds__(128) void kernelA(const float* __restrict__ h,
                                               const float* __restrict__ Wm,
                                               const float* __restrict__ av) {
    __shared__ __align__(16) float hs[64 * 33];   // rows x f-chunk (pad 33: bank = r+f)
    __shared__ __align__(16) float wts[32 * 65];  // f x o (pad 65)

    const int tid  = threadIdx.x;
    const int r0   = blockIdx.x * 64;
    const int ogrp = tid & 7;     // o = ogrp + 8c  (strided -> conflict-free wts reads)
    const int rgrp = tid >> 3;    // 0..15
    const int rb   = rgrp * 4;

    float acc[4][8];
#pragma unroll
    for (int k = 0; k < 4; k++)
#pragma unroll
        for (int c = 0; c < 8; c++) acc[k][c] = 0.0f;

    for (int fc = 0; fc < FIN; fc += 32) {
        // stage W chunk transposed: 64 o x 32 f
        for (int t = tid; t < 512; t += 128) {
            int o = t >> 3, f4 = t & 7;
            float4 v = *(const float4*)(Wm + o * FIN + fc + f4 * 4);
            wts[(f4 * 4 + 0) * 65 + o] = v.x;
            wts[(f4 * 4 + 1) * 65 + o] = v.y;
            wts[(f4 * 4 + 2) * 65 + o] = v.z;
            wts[(f4 * 4 + 3) * 65 + o] = v.w;
        }
        // stage h chunk: 64 rows x 32 f
        for (int t = tid; t < 512; t += 128) {
            int rr = t >> 3, f4 = t & 7;
            float4 v = *(const float4*)(h + (size_t)(r0 + rr) * FIN + fc + f4 * 4);
            hs[rr * 33 + f4 * 4 + 0] = v.x;
            hs[rr * 33 + f4 * 4 + 1] = v.y;
            hs[rr * 33 + f4 * 4 + 2] = v.z;
            hs[rr * 33 + f4 * 4 + 3] = v.w;
        }
        __syncthreads();
#pragma unroll 4
        for (int f = 0; f < 32; f++) {
            float wv[8];
#pragma unroll
            for (int c = 0; c < 8; c++) wv[c] = wts[f * 65 + ogrp + 8 * c];
#pragma unroll
            for (int k = 0; k < 4; k++) {
                float hv = hs[(rb + k) * 33 + f];
#pragma unroll
                for (int c = 0; c < 8; c++) acc[k][c] = fmaf(hv, wv[c], acc[k][c]);
            }
        }
        __syncthreads();
    }

    // epilogue: write Wh, fused s1/s2 (a1 = a[0..63], a2 = a[64..127])
#pragma unroll
    for (int k = 0; k < 4; k++) {
        int r = r0 + rb + k;
        float s1p = 0.0f, s2p = 0.0f;
#pragma unroll
        for (int c = 0; c < 8; c++) {
            int o = ogrp + 8 * c;
            g_Wh[(size_t)r * FO + o] = acc[k][c];
            s1p = fmaf(acc[k][c], __ldg(av + o), s1p);
            s2p = fmaf(acc[k][c], __ldg(av + FO + o), s2p);
        }
#pragma unroll
        for (int off = 4; off >= 1; off >>= 1) {
            s1p += __shfl_down_sync(0xffffffffu, s1p, off, 8);
            s2p += __shfl_down_sync(0xffffffffu, s2p, off, 8);
        }
        if (ogrp == 0) { g_s1[r] = s1p; g_s2[r] = s2p; }
    }
}

// ============================================================
// Kernel B: per-batch max of s2 (upper bound for softmax max)
// ============================================================
__global__ void kernelB() {
    __shared__ float red[256];
    int b = blockIdx.x, tid = threadIdx.x;
    float m = -1e30f;
    for (int j = tid; j < NN; j += 256) m = fmaxf(m, g_s2[b * NN + j]);
    red[tid] = m;
    __syncthreads();
    for (int s = 128; s > 0; s >>= 1) {
        if (tid < s) red[tid] = fmaxf(red[tid], red[tid + s]);
        __syncthreads();
    }
    if (tid == 0) g_s2max[b] = red[0];
}

// ============================================================
// Kernel C: fused masked-softmax attention + P@Wh + ELU
// grid (N/64, B) = (32, 8), 128 threads, thread-tile 4i x 8o
// m_i = LR(s1_i + max_j s2_j) >= every e_ij  (LR monotone) ->
// single pass, exponent <= 0, masked entries contribute p = 0.
// ============================================================
#define TI 64
#define TJ 64
#define PSS 65   // ps stride: bank = (i*65 + j) % 32 = (i + j) % 32

__global__ __launch_bounds__(128) void kernelC(const int* __restrict__ adj,
                                               float* __restrict__ out) {
    __shared__ __align__(16) float whs[TJ * 64];   // 16 KB
    __shared__ float ps[TI * PSS];                  // 16.6 KB
    __shared__ float s1s[TI], ms[TI], ls[TI];

    const int tid = threadIdx.x;
    const int b   = blockIdx.y;
    const int i0  = blockIdx.x * TI;

    if (tid < TI) {
        float s1v = g_s1[b * NN + i0 + tid];
        s1s[tid]  = s1v;
        float t   = s1v + g_s2max[b];
        ms[tid]   = (t > 0.0f) ? t : ALPHA * t;   // row softmax-max upper bound
    }

    const int ogrp = tid & 7, igrp = tid >> 3;
    const int o0 = ogrp * 8, ib = igrp * 4;
    // phase-1 mapping: thread owns one j (coalesced adj), loops 32 i's
    const int jlane = tid & 31;
    const int jh    = tid >> 5;              // 0..3
    const int pj    = jlane + 32 * (jh & 1); // j within tile
    const int ihalf = jh >> 1;               // i-half

    float acc[4][8], lacc[4];
#pragma unroll
    for (int k = 0; k < 4; k++) {
        lacc[k] = 0.0f;
#pragma unroll
        for (int c = 0; c < 8; c++) acc[k][c] = 0.0f;
    }
    __syncthreads();

    const int*   adjrow = adj + ((size_t)b * NN + i0) * NN;
    const float* whb    = g_Wh + (size_t)b * NN * FO;

    for (int jt = 0; jt < NN; jt += TJ) {
        // ---- phase 1a: stage Wh j-tile (coalesced float4) ----
        for (int t = tid; t < TJ * 16; t += 128) {
            int j = t >> 4, o4 = t & 15;
            *(float4*)&whs[j * 64 + o4 * 4] =
                *(const float4*)(whb + (size_t)(jt + j) * FO + o4 * 4);
        }
        // ---- phase 1b: p tile (mask + leakyrelu + exp) ----
        {
            float s2v = __ldg(&g_s2[b * NN + jt + pj]);
#pragma unroll
            for (int ii = 0; ii < 32; ii++) {
                int   i  = ihalf * 32 + ii;
                int   av = adjrow[(size_t)i * NN + jt + pj];
                float e  = s1s[i] + s2v;
                e = (e > 0.0f) ? e : ALPHA * e;
                float p = (av > 0) ? __expf(e - ms[i]) : 0.0f;
                ps[i * PSS + pj] = p;
            }
        }
        __syncthreads();
        // ---- phase 2: rank-1 accumulation over the tile (FMA-bound) ----
#pragma unroll 4
        for (int j = 0; j < TJ; j++) {
            float p0 = ps[(ib + 0) * PSS + j];
            float p1 = ps[(ib + 1) * PSS + j];
            float p2 = ps[(ib + 2) * PSS + j];
            float p3 = ps[(ib + 3) * PSS + j];
            float4 w0 = *(const float4*)&whs[j * 64 + o0];
            float4 w1 = *(const float4*)&whs[j * 64 + o0 + 4];
            float wv[8] = {w0.x, w0.y, w0.z, w0.w, w1.x, w1.y, w1.z, w1.w};
#pragma unroll
            for (int c = 0; c < 8; c++) {
                acc[0][c] = fmaf(p0, wv[c], acc[0][c]);
                acc[1][c] = fmaf(p1, wv[c], acc[1][c]);
                acc[2][c] = fmaf(p2, wv[c], acc[2][c]);
                acc[3][c] = fmaf(p3, wv[c], acc[3][c]);
            }
            lacc[0] += p0; lacc[1] += p1; lacc[2] += p2; lacc[3] += p3;
        }
        __syncthreads();
    }

    // broadcast row sums (every i's l computed identically by its 8 o-threads)
    if (ogrp == 0) {
#pragma unroll
        for (int k = 0; k < 4; k++) ls[ib + k] = lacc[k];
    }
    __syncthreads();

    // normalize + ELU (expm1f for accuracy near 0) + coalesced store
#pragma unroll
    for (int k = 0; k < 4; k++) {
        float linv = 1.0f / ls[ib + k];
        float v[8];
#pragma unroll
        for (int c = 0; c < 8; c++) {
            float x = acc[k][c] * linv;
            v[c] = (x > 0.0f) ? x : expm1f(x);
        }
        float* op = out + ((size_t)b * NN + i0 + ib + k) * FO + o0;
        *(float4*)op       = make_float4(v[0], v[1], v[2], v[3]);
        *(float4*)(op + 4) = make_float4(v[4], v[5], v[6], v[7]);
    }
}

// ============================================================
extern "C" void kernel_launch(void* const* d_in, const int* in_sizes, int n_in,
                              void* d_out, int out_size) {
    const float* h   = nullptr;
    const float* Wm  = nullptr;
    const float* av  = nullptr;
    const int*   adj = nullptr;
    for (int i = 0; i < n_in; i++) {
        switch (in_sizes[i]) {
            case BB * NN * FIN: h   = (const float*)d_in[i]; break;  // 4194304
            case FO * FIN:      Wm  = (const float*)d_in[i]; break;  // 16384
            case 2 * FO:        av  = (const float*)d_in[i]; break;  // 128
            default:
                if (in_sizes[i] == (int)((size_t)BB * NN * NN))
                    adj = (const int*)d_in[i];                        // 33554432
                break;
        }
    }
    float* out = (float*)d_out;

    kernelA<<<256, 128>>>(h, Wm, av);
    kernelB<<<BB, 256>>>();
    kernelC<<<dim3(NN / TI, BB), 128>>>(adj, out);
}

// round 6
// speedup vs baseline: 1.0167x; 1.0167x over previous
#include <cuda_runtime.h>
#include <math.h>

#define BB 8
#define NN 2048
#define FIN 256
#define FO 64
#define ALPHA 0.2f

typedef unsigned long long u64;

// ---- packed f32x2 helpers (sm_103a) ----
__device__ __forceinline__ void ffma2(u64 &d, u64 a, u64 b) {
    asm("fma.rn.f32x2 %0, %1, %2, %0;" : "+l"(d) : "l"(a), "l"(b));
}
__device__ __forceinline__ u64 pack2(float x, float y) {
    u64 r; asm("mov.b64 %0, {%1, %2};" : "=l"(r) : "f"(x), "f"(y)); return r;
}
__device__ __forceinline__ float2 unpack2(u64 v) {
    float2 r; asm("mov.b64 {%0, %1}, %2;" : "=f"(r.x), "=f"(r.y) : "l"(v)); return r;
}
__device__ __forceinline__ u64 mul2(u64 a, u64 b) {
    u64 r; asm("mul.rn.f32x2 %0, %1, %2;" : "=l"(r) : "l"(a), "l"(b)); return r;
}

// ---- scratch (allocation-free rule: __device__ globals) ----
__device__ float g_Wh[BB * NN * FO];
__device__ float g_s1[BB * NN];
__device__ float g_s2[BB * NN];
__device__ float g_s2max[BB];

// ============================================================
// Kernel A: Wh = h @ W^T, fused s1 = Wh.a1, s2 = Wh.a2
// 256 blocks x 64 rows, 256 threads, thread-tile 2r x 8o (f32x2)
// W staged in 2 chunks of 128f x 64o (32 KB); h streamed from GMEM.
// ============================================================
__global__ __launch_bounds__(256, 2) void kernelA(const float* __restrict__ h,
                                                  const float* __restrict__ Wm,
                                                  const float* __restrict__ av) {
    __shared__ __align__(16) float ws[128 * 64];   // [f_local][o], o contiguous

    const int tid  = threadIdx.x;
    const int r0   = blockIdx.x * 64;
    const int ogrp = tid & 7;
    const int rgrp = tid >> 3;       // 0..31
    const int o0   = ogrp * 8;
    const int rb   = rgrp * 2;

    u64 acc[2][4];
#pragma unroll
    for (int k = 0; k < 2; k++)
#pragma unroll
        for (int c = 0; c < 4; c++) acc[k][c] = 0ull;

    const float* h0p = h + (size_t)(r0 + rb) * FIN;
    const float* h1p = h + (size_t)(r0 + rb + 1) * FIN;

    for (int half = 0; half < 2; half++) {
        const int fbase = half * 128;
        // stage W chunk transposed: ws[f][o] = W[o][fbase+f]
        // lanes differ in o -> conflict-free STS
#pragma unroll
        for (int q = 0; q < 8; q++) {
            int idx = q * 256 + tid;
            int o = idx & 63, f4 = idx >> 6;     // f4 in 0..31
            float4 v = *(const float4*)(Wm + o * FIN + fbase + f4 * 4);
            ws[(f4 * 4 + 0) * 64 + o] = v.x;
            ws[(f4 * 4 + 1) * 64 + o] = v.y;
            ws[(f4 * 4 + 2) * 64 + o] = v.z;
            ws[(f4 * 4 + 3) * 64 + o] = v.w;
        }
        __syncthreads();

#pragma unroll 4
        for (int fc = 0; fc < 128; fc += 4) {
            float4 hv0 = *(const float4*)(h0p + fbase + fc);
            float4 hv1 = *(const float4*)(h1p + fbase + fc);
            float ha[4] = {hv0.x, hv0.y, hv0.z, hv0.w};
            float hb[4] = {hv1.x, hv1.y, hv1.z, hv1.w};
#pragma unroll
            for (int q = 0; q < 4; q++) {
                const u64* wp = (const u64*)(ws + (fc + q) * 64 + o0);
                u64 w0 = wp[0], w1 = wp[1], w2 = wp[2], w3 = wp[3];
                u64 pa = pack2(ha[q], ha[q]);
                u64 pb = pack2(hb[q], hb[q]);
                ffma2(acc[0][0], pa, w0); ffma2(acc[0][1], pa, w1);
                ffma2(acc[0][2], pa, w2); ffma2(acc[0][3], pa, w3);
                ffma2(acc[1][0], pb, w0); ffma2(acc[1][1], pb, w1);
                ffma2(acc[1][2], pb, w2); ffma2(acc[1][3], pb, w3);
            }
        }
        __syncthreads();
    }

    // epilogue: write Wh, fused s1/s2 dot + width-8 shfl reduce
#pragma unroll
    for (int k = 0; k < 2; k++) {
        int r = r0 + rb + k;
        float* whp = g_Wh + (size_t)r * FO + o0;
        *(ulonglong2*)(whp)     = make_ulonglong2(acc[k][0], acc[k][1]);
        *(ulonglong2*)(whp + 4) = make_ulonglong2(acc[k][2], acc[k][3]);
        float s1p = 0.0f, s2p = 0.0f;
#pragma unroll
        for (int c = 0; c < 4; c++) {
            float2 f = unpack2(acc[k][c]);
            int o = o0 + 2 * c;
            s1p = fmaf(f.x, __ldg(av + o),          s1p);
            s1p = fmaf(f.y, __ldg(av + o + 1),      s1p);
            s2p = fmaf(f.x, __ldg(av + FO + o),     s2p);
            s2p = fmaf(f.y, __ldg(av + FO + o + 1), s2p);
        }
#pragma unroll
        for (int off = 4; off >= 1; off >>= 1) {
            s1p += __shfl_down_sync(0xffffffffu, s1p, off, 8);
            s2p += __shfl_down_sync(0xffffffffu, s2p, off, 8);
        }
        if (ogrp == 0) { g_s1[r] = s1p; g_s2[r] = s2p; }
    }
}

// ============================================================
// Kernel B: per-batch max of s2 (softmax-max upper bound)
// ============================================================
__global__ void kernelB() {
    __shared__ float red[256];
    int b = blockIdx.x, tid = threadIdx.x;
    float m = -1e30f;
    for (int j = tid; j < NN; j += 256) m = fmaxf(m, g_s2[b * NN + j]);
    red[tid] = m;
    __syncthreads();
    for (int s = 128; s > 0; s >>= 1) {
        if (tid < s) red[tid] = fmaxf(red[tid], red[tid + s]);
        __syncthreads();
    }
    if (tid == 0) g_s2max[b] = red[0];
}

// ============================================================
// Kernel C: fused masked-softmax + P@Wh + ELU
// grid (32, 8), 256 threads, thread-tile 2i x 8o (f32x2),
// register-prefetched adj/s2/Wh pipeline.
// m_i = LR(s1_i + max_j s2_j) >= all e_ij (LR monotone) ->
// single pass, exponent <= 0; masked entries -> p = 0.
// ============================================================
#define TI 64
#define TJ 64
#define PSS 68   // LDS bank = (8*igrp + j) % 32 -> conflict-free
#define WSS 68

__global__ __launch_bounds__(256, 2) void kernelC(const int* __restrict__ adj,
                                                  float* __restrict__ out) {
    __shared__ __align__(16) float whs[TJ * WSS];
    __shared__ __align__(16) float ps[TI * PSS];
    __shared__ float s1s[TI], ms[TI], ls[TI];

    const int tid = threadIdx.x;
    const int b   = blockIdx.y;
    const int i0  = blockIdx.x * TI;

    if (tid < TI) {
        float s1v = g_s1[b * NN + i0 + tid];
        s1s[tid]  = s1v;
        float t   = s1v + g_s2max[b];
        ms[tid]   = (t > 0.0f) ? t : ALPHA * t;
    }

    const int ogrp = tid & 7, igrp = tid >> 3;
    const int o0 = ogrp * 8, ib = igrp * 2;
    const int pi = tid >> 2;            // 0..63 (phase-1 i / whs row)
    const int jc = (tid & 3) * 16;      // 16-wide j / o chunk

    const int*   adjrow = adj + ((size_t)b * NN + i0) * NN;
    const float* whb    = g_Wh + (size_t)b * NN * FO;
    const float* s2b    = g_s2 + b * NN;

    u64 acc[2][4];
#pragma unroll
    for (int k = 0; k < 2; k++)
#pragma unroll
        for (int c = 0; c < 4; c++) acc[k][c] = 0ull;
    float lacc0 = 0.0f, lacc1 = 0.0f;

    // prefetch registers for the current tile
    int4   a4[4];
    float4 s2v[4];
    float4 whv[4];
#pragma unroll
    for (int q = 0; q < 4; q++) {
        a4[q]  = *(const int4*)(adjrow + (size_t)pi * NN + jc + q * 4);
        s2v[q] = *(const float4*)(s2b + jc + q * 4);
        whv[q] = *(const float4*)(whb + (size_t)pi * FO + jc + q * 4);
    }
    __syncthreads();   // s1s/ms visible

    for (int jt = 0; jt < NN; jt += TJ) {
        // ---- phase 1: p tile + Wh tile from prefetched regs ----
        {
            float s1v = s1s[pi], mi = ms[pi];
#pragma unroll
            for (int q = 0; q < 4; q++) {
                int4 a = a4[q]; float4 s = s2v[q];
                float4 pv;
                {
                    float t = s1v + s.x; float e = (t > 0.f) ? t : ALPHA * t;
                    pv.x = (a.x > 0) ? __expf(e - mi) : 0.0f;
                }
                {
                    float t = s1v + s.y; float e = (t > 0.f) ? t : ALPHA * t;
                    pv.y = (a.y > 0) ? __expf(e - mi) : 0.0f;
                }
                {
                    float t = s1v + s.z; float e = (t > 0.f) ? t : ALPHA * t;
                    pv.z = (a.z > 0) ? __expf(e - mi) : 0.0f;
                }
                {
                    float t = s1v + s.w; float e = (t > 0.f) ? t : ALPHA * t;
                    pv.w = (a.w > 0) ? __expf(e - mi) : 0.0f;
                }
                *(float4*)&ps[pi * PSS + jc + q * 4] = pv;
                *(float4*)&whs[pi * WSS + jc + q * 4] = whv[q];
            }
        }
        __syncthreads();

        // ---- prefetch next tile (latency overlaps phase 2) ----
        int jn = jt + TJ;
        if (jn < NN) {
#pragma unroll
            for (int q = 0; q < 4; q++) {
                a4[q]  = *(const int4*)(adjrow + (size_t)pi * NN + jn + jc + q * 4);
                s2v[q] = *(const float4*)(s2b + jn + jc + q * 4);
                whv[q] = *(const float4*)(whb + (size_t)(jn + pi) * FO + jc + q * 4);
            }
        }

        // ---- phase 2: rank-1 accumulation (FFMA2-bound) ----
#pragma unroll 8
        for (int j = 0; j < TJ; j++) {
            float p0 = ps[ib * PSS + j];
            float p1 = ps[(ib + 1) * PSS + j];
            u64 pp0 = pack2(p0, p0);
            u64 pp1 = pack2(p1, p1);
            const u64* wp = (const u64*)(whs + j * WSS + o0);
            u64 w0 = wp[0], w1 = wp[1], w2 = wp[2], w3 = wp[3];
            ffma2(acc[0][0], pp0, w0); ffma2(acc[0][1], pp0, w1);
            ffma2(acc[0][2], pp0, w2); ffma2(acc[0][3], pp0, w3);
            ffma2(acc[1][0], pp1, w0); ffma2(acc[1][1], pp1, w1);
            ffma2(acc[1][2], pp1, w2); ffma2(acc[1][3], pp1, w3);
            lacc0 += p0; lacc1 += p1;
        }
        __syncthreads();
    }

    // row sums (all 8 o-threads of an i computed identical lacc)
    if (ogrp == 0) { ls[ib] = lacc0; ls[ib + 1] = lacc1; }
    __syncthreads();

    // normalize + ELU + coalesced store
#pragma unroll
    for (int k = 0; k < 2; k++) {
        float linv = 1.0f / ls[ib + k];
        u64 lv = pack2(linv, linv);
        float v[8];
#pragma unroll
        for (int c = 0; c < 4; c++) {
            float2 f = unpack2(mul2(acc[k][c], lv));
            v[2 * c]     = (f.x > 0.0f) ? f.x : expm1f(f.x);
            v[2 * c + 1] = (f.y > 0.0f) ? f.y : expm1f(f.y);
        }
        float* op = out + ((size_t)b * NN + i0 + ib + k) * FO + o0;
        *(float4*)op       = make_float4(v[0], v[1], v[2], v[3]);
        *(float4*)(op + 4) = make_float4(v[4], v[5], v[6], v[7]);
    }
}

// ============================================================
extern "C" void kernel_launch(void* const* d_in, const int* in_sizes, int n_in,
                              void* d_out, int out_size) {
    const float* h   = nullptr;
    const float* Wm  = nullptr;
    const float* av  = nullptr;
    const int*   adj = nullptr;
    for (int i = 0; i < n_in; i++) {
        switch (in_sizes[i]) {
            case BB * NN * FIN: h  = (const float*)d_in[i]; break;
            case FO * FIN:      Wm = (const float*)d_in[i]; break;
            case 2 * FO:        av = (const float*)d_in[i]; break;
            default:
                if (in_sizes[i] == (int)((size_t)BB * NN * NN))
                    adj = (const int*)d_in[i];
                break;
        }
    }
    float* out = (float*)d_out;

    kernelA<<<256, 256>>>(h, Wm, av);
    kernelB<<<BB, 256>>>();
    kernelC<<<dim3(NN / TI, BB), 256>>>(adj, out);
}

// round 7
// speedup vs baseline: 1.9108x; 1.8794x over previous
#include <cuda_runtime.h>
#include <math.h>

#define BB 8
#define NN 2048
#define FIN 256
#define FO 64
#define ALPHA 0.2f

typedef unsigned long long u64;

// ---- packed f32x2 helpers ----
__device__ __forceinline__ void ffma2(u64 &d, u64 a, u64 b) {
    asm("fma.rn.f32x2 %0, %1, %2, %0;" : "+l"(d) : "l"(a), "l"(b));
}
__device__ __forceinline__ u64 pack2s(float x) {           // (x, x)
    u64 r; asm("mov.b64 %0, {%1, %1};" : "=l"(r) : "f"(x)); return r;
}
__device__ __forceinline__ float2 unpack2(u64 v) {
    float2 r; asm("mov.b64 {%0, %1}, %2;" : "=f"(r.x), "=f"(r.y) : "l"(v)); return r;
}

// ---- scratch ----
__device__ float g_Wh[BB * NN * FO];
__device__ float g_s1[BB * NN];
__device__ float g_s2[BB * NN];
__device__ float g_s2max[BB];
__device__ float g_pacc[2 * BB * NN * FO];   // j-half partial sums
__device__ float g_pl[2 * BB * NN];          // j-half partial row sums

// ============================================================
// Kernel A: Wh = h @ W^T, fused s1/s2.  256 blocks x 64 rows,
// 128 threads, thread-tile 4r x 8o (f32x2). h staged via smem
// ONCE (no duplicated LDG); W transposed + slot-swizzled.
// ============================================================
__global__ __launch_bounds__(128) void kernelA(const float* __restrict__ h,
                                               const float* __restrict__ Wm,
                                               const float* __restrict__ av) {
    __shared__ __align__(16) float hs[64 * 68];   // [row][f] pad 68
    __shared__ __align__(16) float ws[64 * 64];   // [f][o] slot-swizzled

    const int tid = threadIdx.x;
    const int r0  = blockIdx.x * 64;
    const int og  = tid & 7, igq = tid >> 3;      // igq 0..15 -> rows igq*4..+3

    // swizzled word offsets for this thread's two 16B w-chunks
    const int u0 = 2 * og,      u0p = u0 ^ (u0 >> 3);
    const int u1 = 2 * og + 1,  u1p = u1 ^ (u1 >> 3);
    const int w0off = u0p * 4,  w1off = u1p * 4;

    // W staging constants: thread = (oo, fh)
    const int oo = tid >> 1, fh = tid & 1;
    const int wu = oo >> 2, wup = wu ^ (wu >> 3);
    const int wcol = wup * 4 + (oo & 3);

    u64 acc[4][4];
#pragma unroll
    for (int k = 0; k < 4; k++)
#pragma unroll
        for (int c = 0; c < 4; c++) acc[k][c] = 0ull;

    for (int fc = 0; fc < FIN; fc += 64) {
        __syncthreads();   // protect prev-iter reads
        // stage h: 64 rows x 64 f, cooperative, each byte once
#pragma unroll
        for (int k = 0; k < 8; k++) {
            int c = tid + k * 128;
            int row = c >> 4, u = c & 15;
            float4 v = *(const float4*)(h + (size_t)(r0 + row) * FIN + fc + u * 4);
            *(float4*)&hs[row * 68 + u * 4] = v;
        }
        // stage W transposed: ws[f][o] slot-swizzled
#pragma unroll
        for (int q4 = 0; q4 < 8; q4++) {
            float4 v = *(const float4*)(Wm + oo * FIN + fc + fh * 32 + q4 * 4);
            int fb = fh * 32 + q4 * 4;
            ws[(fb + 0) * 64 + wcol] = v.x;
            ws[(fb + 1) * 64 + wcol] = v.y;
            ws[(fb + 2) * 64 + wcol] = v.z;
            ws[(fb + 3) * 64 + wcol] = v.w;
        }
        __syncthreads();

        const float* hp0 = hs + (igq * 4 + 0) * 68;
        const float* hp1 = hs + (igq * 4 + 1) * 68;
        const float* hp2 = hs + (igq * 4 + 2) * 68;
        const float* hp3 = hs + (igq * 4 + 3) * 68;
#pragma unroll 8
        for (int f = 0; f < 64; f++) {
            u64 pa0 = pack2s(hp0[f]);
            u64 pa1 = pack2s(hp1[f]);
            u64 pa2 = pack2s(hp2[f]);
            u64 pa3 = pack2s(hp3[f]);
            ulonglong2 wa = *(const ulonglong2*)(ws + f * 64 + w0off);
            ulonglong2 wb = *(const ulonglong2*)(ws + f * 64 + w1off);
            ffma2(acc[0][0], pa0, wa.x); ffma2(acc[0][1], pa0, wa.y);
            ffma2(acc[0][2], pa0, wb.x); ffma2(acc[0][3], pa0, wb.y);
            ffma2(acc[1][0], pa1, wa.x); ffma2(acc[1][1], pa1, wa.y);
            ffma2(acc[1][2], pa1, wb.x); ffma2(acc[1][3], pa1, wb.y);
            ffma2(acc[2][0], pa2, wa.x); ffma2(acc[2][1], pa2, wa.y);
            ffma2(acc[2][2], pa2, wb.x); ffma2(acc[2][3], pa2, wb.y);
            ffma2(acc[3][0], pa3, wa.x); ffma2(acc[3][1], pa3, wa.y);
            ffma2(acc[3][2], pa3, wb.x); ffma2(acc[3][3], pa3, wb.y);
        }
    }

    // epilogue: Wh store + fused s1/s2
#pragma unroll
    for (int k = 0; k < 4; k++) {
        int r = r0 + igq * 4 + k;
        float* whp = g_Wh + (size_t)r * FO + og * 8;
        *(ulonglong2*)(whp)     = make_ulonglong2(acc[k][0], acc[k][1]);
        *(ulonglong2*)(whp + 4) = make_ulonglong2(acc[k][2], acc[k][3]);
        float s1p = 0.0f, s2p = 0.0f;
#pragma unroll
        for (int c = 0; c < 4; c++) {
            float2 f2 = unpack2(acc[k][c]);
            int o = og * 8 + 2 * c;
            s1p = fmaf(f2.x, __ldg(av + o),          s1p);
            s1p = fmaf(f2.y, __ldg(av + o + 1),      s1p);
            s2p = fmaf(f2.x, __ldg(av + FO + o),     s2p);
            s2p = fmaf(f2.y, __ldg(av + FO + o + 1), s2p);
        }
#pragma unroll
        for (int off = 4; off >= 1; off >>= 1) {
            s1p += __shfl_down_sync(0xffffffffu, s1p, off, 8);
            s2p += __shfl_down_sync(0xffffffffu, s2p, off, 8);
        }
        if (og == 0) { g_s1[r] = s1p; g_s2[r] = s2p; }
    }
}

// ============================================================
// Kernel B: per-batch max of s2 (softmax-max upper bound)
// ============================================================
__global__ void kernelB() {
    __shared__ float red[256];
    int b = blockIdx.x, tid = threadIdx.x;
    float m = -1e30f;
    for (int j = tid; j < NN; j += 256) m = fmaxf(m, g_s2[b * NN + j]);
    red[tid] = m;
    __syncthreads();
    for (int s = 128; s > 0; s >>= 1) {
        if (tid < s) red[tid] = fmaxf(red[tid], red[tid + s]);
        __syncthreads();
    }
    if (tid == 0) g_s2max[b] = red[0];
}

// ============================================================
// Kernel C: masked-softmax attention, partial over a j-half.
// grid (jh=2, it=16, b=8) = 256 blocks, 256 threads.
// TI=128 rows, j-range 1024 = 16 tiles of 64.
// Phase 2: thread-tile 4i x 8o (f32x2), 6 L1 wf / warp-j.
// m_i = LR(s1_i + max_j s2_j) >= all e_ij  (LR monotone) ->
// single pass, exponent <= 0, halves combine by addition.
// ============================================================
#define TI 128
#define TJ 64

__global__ __launch_bounds__(256, 2) void kernelC(const int* __restrict__ adj,
                                                  const float* __restrict__ dummy) {
    __shared__ float ps[TI * 64];                  // 32 KB  [i][j]
    __shared__ __align__(16) float whs[TJ * 64];   // 16 KB  [j][o] swizzled
    // 48 KB static total -> 2 blocks/SM

    const int tid = threadIdx.x;
    const int jh  = blockIdx.x;           // j half
    const int i0  = blockIdx.y * TI;
    const int b   = blockIdx.z;
    const int j0  = jh * (NN / 2);

    // phase-1 mapping
    const int jl  = tid & 63, ig4 = tid >> 6;     // ig4 0..3 -> 32 i's each
    // phase-2 mapping
    const int og  = tid & 7, igq = tid >> 3;      // igq 0..31 -> rows igq*4..+3
    const int u0 = 2 * og,     u0p = u0 ^ (u0 >> 3);
    const int u1 = 2 * og + 1, u1p = u1 ^ (u1 >> 3);
    const int w0off = u0p * 4, w1off = u1p * 4;

    const float  M    = g_s2max[b];
    const float* s1b  = g_s1 + b * NN + i0;
    const float* s2b  = g_s2 + b * NN;
    const float* whb  = g_Wh + (size_t)b * NN * FO;
    const int*   adjb = adj + ((size_t)b * NN + i0) * NN;

    u64 acc[4][4];
    float lacc[4];
#pragma unroll
    for (int k = 0; k < 4; k++) {
        lacc[k] = 0.0f;
#pragma unroll
        for (int c = 0; c < 4; c++) acc[k][c] = 0ull;
    }

    for (int t = 0; t < NN / 2 / TJ; t++) {
        const int jt = j0 + t * TJ;
        // ---- stage whs (swizzled slots) ----
#pragma unroll
        for (int k = 0; k < 4; k++) {
            int c = tid + k * 256;
            int jr = c >> 4, u = c & 15, up = u ^ (u >> 3);
            float4 v = *(const float4*)(whb + (size_t)(jt + jr) * FO + u * 4);
            *(float4*)&whs[jr * 64 + up * 4] = v;
        }
        // ---- p tile: lane = j (coalesced adj), loop 32 i ----
        {
            float s2j = s2b[jt + jl];
            const int* ap = adjb + jt + jl;
#pragma unroll 8
            for (int ii = 0; ii < 32; ii++) {
                int i = ig4 * 32 + ii;
                int a = ap[(size_t)i * NN];
                float s1v = __ldg(s1b + i);                 // warp-uniform
                float mt  = s1v + M;
                float mi  = (mt > 0.0f) ? mt : ALPHA * mt;  // row max bound
                float tt  = s1v + s2j;
                float e   = (tt > 0.0f) ? tt : ALPHA * tt;
                float p   = (a > 0) ? __expf(e - mi) : 0.0f;
                ps[i * 64 + jl] = p;
            }
        }
        __syncthreads();
        // ---- phase 2: 4i x 8o f32x2 rank-1 accumulation ----
        {
            const float* psp0 = ps + (igq * 4 + 0) * 64;
            const float* psp1 = ps + (igq * 4 + 1) * 64;
            const float* psp2 = ps + (igq * 4 + 2) * 64;
            const float* psp3 = ps + (igq * 4 + 3) * 64;
#pragma unroll 16
            for (int j = 0; j < TJ; j++) {
                float p0 = psp0[j], p1 = psp1[j], p2 = psp2[j], p3 = psp3[j];
                lacc[0] += p0; lacc[1] += p1; lacc[2] += p2; lacc[3] += p3;
                u64 q0 = pack2s(p0), q1 = pack2s(p1), q2 = pack2s(p2), q3 = pack2s(p3);
                ulonglong2 wa = *(const ulonglong2*)(whs + j * 64 + w0off);
                ulonglong2 wb = *(const ulonglong2*)(whs + j * 64 + w1off);
                ffma2(acc[0][0], q0, wa.x); ffma2(acc[0][1], q0, wa.y);
                ffma2(acc[0][2], q0, wb.x); ffma2(acc[0][3], q0, wb.y);
                ffma2(acc[1][0], q1, wa.x); ffma2(acc[1][1], q1, wa.y);
                ffma2(acc[1][2], q1, wb.x); ffma2(acc[1][3], q1, wb.y);
                ffma2(acc[2][0], q2, wa.x); ffma2(acc[2][1], q2, wa.y);
                ffma2(acc[2][2], q2, wb.x); ffma2(acc[2][3], q2, wb.y);
                ffma2(acc[3][0], q3, wa.x); ffma2(acc[3][1], q3, wa.y);
                ffma2(acc[3][2], q3, wb.x); ffma2(acc[3][3], q3, wb.y);
            }
        }
        __syncthreads();
    }

    // ---- store partials ----
    float* pacc = g_pacc + (size_t)jh * BB * NN * FO + ((size_t)b * NN + i0) * FO;
#pragma unroll
    for (int k = 0; k < 4; k++) {
        int i = igq * 4 + k;
        float* p = pacc + (size_t)i * FO + og * 8;
        *(ulonglong2*)(p)     = make_ulonglong2(acc[k][0], acc[k][1]);
        *(ulonglong2*)(p + 4) = make_ulonglong2(acc[k][2], acc[k][3]);
    }
    if (og == 0) {
#pragma unroll
        for (int k = 0; k < 4; k++)
            g_pl[jh * BB * NN + b * NN + i0 + igq * 4 + k] = lacc[k];
    }
}

// ============================================================
// Kernel D: combine halves, normalize, ELU, store
// ============================================================
__global__ __launch_bounds__(256) void kernelD(float* __restrict__ out) {
    int idx = blockIdx.x * 256 + threadIdx.x;   // float4 index, 262144 total
    int row = idx >> 4;                         // FO/4 = 16 float4 per row
    float l  = g_pl[row] + g_pl[BB * NN + row];
    float rl = 1.0f / l;
    float4 a0 = *(const float4*)(g_pacc + (size_t)idx * 4);
    float4 a1 = *(const float4*)(g_pacc + (size_t)BB * NN * FO + (size_t)idx * 4);
    float4 r;
    r.x = (a0.x + a1.x) * rl; r.x = (r.x > 0.0f) ? r.x : expm1f(r.x);
    r.y = (a0.y + a1.y) * rl; r.y = (r.y > 0.0f) ? r.y : expm1f(r.y);
    r.z = (a0.z + a1.z) * rl; r.z = (r.z > 0.0f) ? r.z : expm1f(r.z);
    r.w = (a0.w + a1.w) * rl; r.w = (r.w > 0.0f) ? r.w : expm1f(r.w);
    *(float4*)(out + (size_t)idx * 4) = r;
}

// ============================================================
extern "C" void kernel_launch(void* const* d_in, const int* in_sizes, int n_in,
                              void* d_out, int out_size) {
    const float* h   = nullptr;
    const float* Wm  = nullptr;
    const float* av  = nullptr;
    const int*   adj = nullptr;
    for (int i = 0; i < n_in; i++) {
        switch (in_sizes[i]) {
            case BB * NN * FIN: h  = (const float*)d_in[i]; break;
            case FO * FIN:      Wm = (const float*)d_in[i]; break;
            case 2 * FO:        av = (const float*)d_in[i]; break;
            default:
                if (in_sizes[i] == (int)((size_t)BB * NN * NN))
                    adj = (const int*)d_in[i];
                break;
        }
    }
    float* out = (float*)d_out;

    kernelA<<<256, 128>>>(h, Wm, av);
    kernelB<<<BB, 256>>>();
    kernelC<<<dim3(2, 16, BB), 256>>>(adj, nullptr);
    kernelD<<<BB * NN * FO / 4 / 256, 256>>>(out);
}

// round 12
// speedup vs baseline: 2.3365x; 1.2228x over previous
#include <cuda_runtime.h>
#include <cuda_bf16.h>
#include <math.h>

#define BB 8
#define NN 2048
#define FIN 256
#define FO 64
#define ALPHA 0.2f

typedef unsigned long long u64;
typedef unsigned int u32;

// ---- packed f32x2 helpers (kernelA) ----
__device__ __forceinline__ void ffma2(u64 &d, u64 a, u64 b) {
    asm("fma.rn.f32x2 %0, %1, %2, %0;" : "+l"(d) : "l"(a), "l"(b));
}
__device__ __forceinline__ u64 pack2s(float x) {
    u64 r; asm("mov.b64 %0, {%1, %1};" : "=l"(r) : "f"(x)); return r;
}
__device__ __forceinline__ float2 unpack2(u64 v) {
    float2 r; asm("mov.b64 {%0, %1}, %2;" : "=f"(r.x), "=f"(r.y) : "l"(v)); return r;
}

// ---- HMMA m16n8k16 bf16 (base PTX, compiles for compute_103) ----
__device__ __forceinline__ void mma_bf16(float* c, const u32* a, u32 b0, u32 b1) {
    asm("mma.sync.aligned.m16n8k16.row.col.f32.bf16.bf16.f32 "
        "{%0,%1,%2,%3}, {%4,%5,%6,%7}, {%8,%9}, {%0,%1,%2,%3};"
        : "+f"(c[0]), "+f"(c[1]), "+f"(c[2]), "+f"(c[3])
        : "r"(a[0]), "r"(a[1]), "r"(a[2]), "r"(a[3]), "r"(b0), "r"(b1));
}

// ---- scratch ----
__device__ float g_Wh[BB * NN * FO];
__device__ float g_s1[BB * NN];
__device__ float g_s2[BB * NN];
__device__ float g_s2max[BB];
__device__ __nv_bfloat16 g_WhT_hi[BB * FO * NN];   // [b][o][j]
__device__ __nv_bfloat16 g_WhT_lo[BB * FO * NN];
__device__ float g_pacc[2 * BB * NN * FO];          // j-half partials
__device__ float g_pl[2 * BB * NN];

// ============================================================
// Kernel A: Wh = h @ W^T, fused s1/s2 (f32x2) — proven
// ============================================================
__global__ __launch_bounds__(128) void kernelA(const float* __restrict__ h,
                                               const float* __restrict__ Wm,
                                               const float* __restrict__ av) {
    __shared__ __align__(16) float hs[64 * 68];
    __shared__ __align__(16) float ws[64 * 64];

    const int tid = threadIdx.x;
    const int r0  = blockIdx.x * 64;
    const int og  = tid & 7, igq = tid >> 3;

    const int u0 = 2 * og,      u0p = u0 ^ (u0 >> 3);
    const int u1 = 2 * og + 1,  u1p = u1 ^ (u1 >> 3);
    const int w0off = u0p * 4,  w1off = u1p * 4;

    const int oo = tid >> 1, fh = tid & 1;
    const int wu = oo >> 2, wup = wu ^ (wu >> 3);
    const int wcol = wup * 4 + (oo & 3);

    u64 acc[4][4];
#pragma unroll
    for (int k = 0; k < 4; k++)
#pragma unroll
        for (int c = 0; c < 4; c++) acc[k][c] = 0ull;

    for (int fc = 0; fc < FIN; fc += 64) {
        __syncthreads();
#pragma unroll
        for (int k = 0; k < 8; k++) {
            int c = tid + k * 128;
            int row = c >> 4, u = c & 15;
            float4 v = *(const float4*)(h + (size_t)(r0 + row) * FIN + fc + u * 4);
            *(float4*)&hs[row * 68 + u * 4] = v;
        }
#pragma unroll
        for (int q4 = 0; q4 < 8; q4++) {
            float4 v = *(const float4*)(Wm + oo * FIN + fc + fh * 32 + q4 * 4);
            int fb = fh * 32 + q4 * 4;
            ws[(fb + 0) * 64 + wcol] = v.x;
            ws[(fb + 1) * 64 + wcol] = v.y;
            ws[(fb + 2) * 64 + wcol] = v.z;
            ws[(fb + 3) * 64 + wcol] = v.w;
        }
        __syncthreads();

        const float* hp0 = hs + (igq * 4 + 0) * 68;
        const float* hp1 = hs + (igq * 4 + 1) * 68;
        const float* hp2 = hs + (igq * 4 + 2) * 68;
        const float* hp3 = hs + (igq * 4 + 3) * 68;
#pragma unroll 8
        for (int f = 0; f < 64; f++) {
            u64 pa0 = pack2s(hp0[f]);
            u64 pa1 = pack2s(hp1[f]);
            u64 pa2 = pack2s(hp2[f]);
            u64 pa3 = pack2s(hp3[f]);
            ulonglong2 wa = *(const ulonglong2*)(ws + f * 64 + w0off);
            ulonglong2 wb = *(const ulonglong2*)(ws + f * 64 + w1off);
            ffma2(acc[0][0], pa0, wa.x); ffma2(acc[0][1], pa0, wa.y);
            ffma2(acc[0][2], pa0, wb.x); ffma2(acc[0][3], pa0, wb.y);
            ffma2(acc[1][0], pa1, wa.x); ffma2(acc[1][1], pa1, wa.y);
            ffma2(acc[1][2], pa1, wb.x); ffma2(acc[1][3], pa1, wb.y);
            ffma2(acc[2][0], pa2, wa.x); ffma2(acc[2][1], pa2, wa.y);
            ffma2(acc[2][2], pa2, wb.x); ffma2(acc[2][3], pa2, wb.y);
            ffma2(acc[3][0], pa3, wa.x); ffma2(acc[3][1], pa3, wa.y);
            ffma2(acc[3][2], pa3, wb.x); ffma2(acc[3][3], pa3, wb.y);
        }
    }

#pragma unroll
    for (int k = 0; k < 4; k++) {
        int r = r0 + igq * 4 + k;
        float* whp = g_Wh + (size_t)r * FO + og * 8;
        *(ulonglong2*)(whp)     = make_ulonglong2(acc[k][0], acc[k][1]);
        *(ulonglong2*)(whp + 4) = make_ulonglong2(acc[k][2], acc[k][3]);
        float s1p = 0.0f, s2p = 0.0f;
#pragma unroll
        for (int c = 0; c < 4; c++) {
            float2 f2 = unpack2(acc[k][c]);
            int o = og * 8 + 2 * c;
            s1p = fmaf(f2.x, __ldg(av + o),          s1p);
            s1p = fmaf(f2.y, __ldg(av + o + 1),      s1p);
            s2p = fmaf(f2.x, __ldg(av + FO + o),     s2p);
            s2p = fmaf(f2.y, __ldg(av + FO + o + 1), s2p);
        }
#pragma unroll
        for (int off = 4; off >= 1; off >>= 1) {
            s1p += __shfl_down_sync(0xffffffffu, s1p, off, 8);
            s2p += __shfl_down_sync(0xffffffffu, s2p, off, 8);
        }
        if (og == 0) { g_s1[r] = s1p; g_s2[r] = s2p; }
    }
}

// ============================================================
// Kernel B: per-batch max of s2
// ============================================================
__global__ void kernelB() {
    __shared__ float red[256];
    int b = blockIdx.x, tid = threadIdx.x;
    float m = -1e30f;
    for (int j = tid; j < NN; j += 256) m = fmaxf(m, g_s2[b * NN + j]);
    red[tid] = m;
    __syncthreads();
    for (int s = 128; s > 0; s >>= 1) {
        if (tid < s) red[tid] = fmaxf(red[tid], red[tid + s]);
        __syncthreads();
    }
    if (tid == 0) g_s2max[b] = red[0];
}

// ============================================================
// Kernel A2: Wh -> WhT[b][o][j], split bf16 hi+lo
// (scalar STS into 65-stride tile: 260 B row pitch is NOT
//  16B-aligned -> float4 store here trapped in R11)
// ============================================================
__global__ __launch_bounds__(256) void kernelA2() {
    __shared__ float sm[64 * 65];
    const int tid = threadIdx.x;
    const int j0  = blockIdx.x * 64;
    const int b   = blockIdx.y;

    {
        int j = tid >> 2, u = tid & 3;
        const float* src = g_Wh + ((size_t)b * NN + j0 + j) * FO + u * 16;
        float* dst = sm + j * 65 + u * 16;
#pragma unroll
        for (int q = 0; q < 4; q++) {
            float4 v = *(const float4*)(src + q * 4);   // gmem LDG.128 ok
            dst[q * 4 + 0] = v.x;                        // scalar STS (aligned)
            dst[q * 4 + 1] = v.y;
            dst[q * 4 + 2] = v.z;
            dst[q * 4 + 3] = v.w;
        }
    }
    __syncthreads();
    {
        int o = tid >> 2, q = tid & 3;
        u32 hiw[8], low[8];
#pragma unroll
        for (int p = 0; p < 8; p++) {
            float f0 = sm[(q * 16 + 2 * p)     * 65 + o];
            float f1 = sm[(q * 16 + 2 * p + 1) * 65 + o];
            __nv_bfloat162 h2 = __float22bfloat162_rn(make_float2(f0, f1));
            float2 hf = __bfloat1622float2(h2);
            __nv_bfloat162 l2 = __float22bfloat162_rn(make_float2(f0 - hf.x, f1 - hf.y));
            hiw[p] = *(u32*)&h2;
            low[p] = *(u32*)&l2;
        }
        size_t idx = ((size_t)b * FO + o) * NN + j0 + q * 16;
        *(uint4*)(g_WhT_hi + idx)     = make_uint4(hiw[0], hiw[1], hiw[2], hiw[3]);
        *(uint4*)(g_WhT_hi + idx + 8) = make_uint4(hiw[4], hiw[5], hiw[6], hiw[7]);
        *(uint4*)(g_WhT_lo + idx)     = make_uint4(low[0], low[1], low[2], low[3]);
        *(uint4*)(g_WhT_lo + idx + 8) = make_uint4(low[4], low[5], low[6], low[7]);
    }
}

// ============================================================
// Kernel C: masked softmax + P@Wh via HMMA bf16 3-term split.
// grid (jh=2, 16 i-tiles, 8 b) = 256 blocks, 256 thr (8 warps).
// Warp w owns i rows w*16..+15 for phase1 AND mma (m16 tiles).
// P/W tiles in smem, stride 72 bf16 -> frag LDS bank = 4g+t
// (conflict-free). m_i = LR(s1_i + max_j s2_j) upper bound ->
// single pass, halves additive; kernelD combines.
// ============================================================
#define SP 72
#define DSMEM_BF16 (384 * 72)   // Phi,Plo: 128*72 each; Whi,Wlo: 64*72 each
#define DSMEM_BYTES (DSMEM_BF16 * 2)

__global__ __launch_bounds__(256) void kernelC(const int* __restrict__ adj) {
    extern __shared__ __align__(16) __nv_bfloat16 dsm[];
    __nv_bfloat16* Phi = dsm;
    __nv_bfloat16* Plo = dsm + 128 * SP;
    __nv_bfloat16* Whi = dsm + 256 * SP;
    __nv_bfloat16* Wlo = dsm + 256 * SP + 64 * SP;
    __shared__ float ls[128];

    const int tid  = threadIdx.x;
    const int wid  = tid >> 5;
    const int lane = tid & 31;
    const int g    = lane >> 2, t = lane & 3;
    const int jh   = blockIdx.x;
    const int i0   = blockIdx.y * 128;
    const int b    = blockIdx.z;
    const int j0   = jh * (NN / 2);

    // per-thread row constants
    float s1v[16], mi[16], lsum[16];
    {
        const float M = g_s2max[b];
#pragma unroll
        for (int ii = 0; ii < 16; ii++) {
            float s1 = __ldg(&g_s1[b * NN + i0 + wid * 16 + ii]);
            s1v[ii] = s1;
            float tt = s1 + M;
            mi[ii] = fmaxf(tt, ALPHA * tt);
            lsum[ii] = 0.0f;
        }
    }

    const int*   adjb = adj + ((size_t)b * NN + i0) * NN;
    const float* s2b  = g_s2 + b * NN;
    const __nv_bfloat16* bhiB = g_WhT_hi + (size_t)b * FO * NN;
    const __nv_bfloat16* bloB = g_WhT_lo + (size_t)b * FO * NN;

    float acc[8][4];
#pragma unroll
    for (int nf = 0; nf < 8; nf++)
#pragma unroll
        for (int c = 0; c < 4; c++) acc[nf][c] = 0.0f;

    for (int tch = 0; tch < NN / 2 / 64; tch++) {
        const int jt = j0 + tch * 64;

        // ---- stage W tiles (coalesced 16B loads, 144B smem pitch = 9x16B ok) ----
        {
            int o = tid >> 2, q = tid & 3;
            const __nv_bfloat16* sh = bhiB + (size_t)o * NN + jt + q * 16;
            const __nv_bfloat16* sl = bloB + (size_t)o * NN + jt + q * 16;
            *(uint4*)&Whi[o * SP + q * 16]     = *(const uint4*)(sh);
            *(uint4*)&Whi[o * SP + q * 16 + 8] = *(const uint4*)(sh + 8);
            *(uint4*)&Wlo[o * SP + q * 16]     = *(const uint4*)(sl);
            *(uint4*)&Wlo[o * SP + q * 16 + 8] = *(const uint4*)(sl + 8);
        }
        // ---- phase 1: p = exp(LR(s1+s2)-m) masked, hi/lo split ----
        {
            float2 s2j = *(const float2*)(s2b + jt + 2 * lane);
#pragma unroll
            for (int ii = 0; ii < 16; ii++) {
                int i = wid * 16 + ii;
                int2 a = *(const int2*)(adjb + (size_t)i * NN + jt + 2 * lane);
                float e0 = s1v[ii] + s2j.x;
                float e1 = s1v[ii] + s2j.y;
                e0 = fmaxf(e0, ALPHA * e0);
                e1 = fmaxf(e1, ALPHA * e1);
                float p0 = (a.x > 0) ? __expf(e0 - mi[ii]) : 0.0f;
                float p1 = (a.y > 0) ? __expf(e1 - mi[ii]) : 0.0f;
                lsum[ii] += p0 + p1;
                __nv_bfloat162 h2 = __float22bfloat162_rn(make_float2(p0, p1));
                float2 hf = __bfloat1622float2(h2);
                __nv_bfloat162 l2 =
                    __float22bfloat162_rn(make_float2(p0 - hf.x, p1 - hf.y));
                *(u32*)&Phi[i * SP + 2 * lane] = *(u32*)&h2;
                *(u32*)&Plo[i * SP + 2 * lane] = *(u32*)&l2;
            }
        }
        __syncthreads();

        // ---- phase 2: HMMA 3-term accumulation ----
        {
            const int ib = wid * 16;
#pragma unroll
            for (int kf = 0; kf < 4; kf++) {
                int k0 = kf * 16;
                int ra  = (ib + g) * SP + k0 + 2 * t;
                int rb2 = (ib + g + 8) * SP + k0 + 2 * t;
                u32 ah[4], al[4];
                ah[0] = *(const u32*)&Phi[ra];      ah[1] = *(const u32*)&Phi[rb2];
                ah[2] = *(const u32*)&Phi[ra + 8];  ah[3] = *(const u32*)&Phi[rb2 + 8];
                al[0] = *(const u32*)&Plo[ra];      al[1] = *(const u32*)&Plo[rb2];
                al[2] = *(const u32*)&Plo[ra + 8];  al[3] = *(const u32*)&Plo[rb2 + 8];
#pragma unroll
                for (int nf = 0; nf < 8; nf++) {
                    int bo = (nf * 8 + g) * SP + k0 + 2 * t;
                    u32 bh0 = *(const u32*)&Whi[bo], bh1 = *(const u32*)&Whi[bo + 8];
                    u32 bl0 = *(const u32*)&Wlo[bo], bl1 = *(const u32*)&Wlo[bo + 8];
                    mma_bf16(acc[nf], ah, bh0, bh1);
                    mma_bf16(acc[nf], al, bh0, bh1);
                    mma_bf16(acc[nf], ah, bl0, bl1);
                }
            }
        }
        __syncthreads();
    }

    // ---- row sums -> shared / global partial ----
#pragma unroll
    for (int ii = 0; ii < 16; ii++) {
        float v = lsum[ii];
#pragma unroll
        for (int off = 16; off >= 1; off >>= 1)
            v += __shfl_xor_sync(0xffffffffu, v, off);
        if (lane == 0) ls[wid * 16 + ii] = v;
    }
    __syncthreads();
    if (tid < 128)
        g_pl[jh * BB * NN + b * NN + i0 + tid] = ls[tid];

    // ---- store accumulator partials (D frag map: c0=(g,2t) c1=(g,2t+1)
    //      c2=(g+8,2t) c3=(g+8,2t+1)) ----
    float* pacc = g_pacc + (size_t)jh * BB * NN * FO
                + ((size_t)b * NN + i0 + wid * 16) * FO;
#pragma unroll
    for (int nf = 0; nf < 8; nf++) {
        int col = nf * 8 + 2 * t;
        *(float2*)&pacc[(size_t)g * FO + col]       = make_float2(acc[nf][0], acc[nf][1]);
        *(float2*)&pacc[(size_t)(g + 8) * FO + col] = make_float2(acc[nf][2], acc[nf][3]);
    }
}

// ============================================================
// Kernel D: combine halves, normalize, ELU, store
// ============================================================
__global__ __launch_bounds__(256) void kernelD(float* __restrict__ out) {
    int idx = blockIdx.x * 256 + threadIdx.x;   // float4 index
    int row = idx >> 4;
    float l  = g_pl[row] + g_pl[BB * NN + row];
    float rl = 1.0f / l;
    float4 a0 = *(const float4*)(g_pacc + (size_t)idx * 4);
    float4 a1 = *(const float4*)(g_pacc + (size_t)BB * NN * FO + (size_t)idx * 4);
    float4 r;
    r.x = (a0.x + a1.x) * rl; r.x = (r.x > 0.0f) ? r.x : expm1f(r.x);
    r.y = (a0.y + a1.y) * rl; r.y = (r.y > 0.0f) ? r.y : expm1f(r.y);
    r.z = (a0.z + a1.z) * rl; r.z = (r.z > 0.0f) ? r.z : expm1f(r.z);
    r.w = (a0.w + a1.w) * rl; r.w = (r.w > 0.0f) ? r.w : expm1f(r.w);
    *(float4*)(out + (size_t)idx * 4) = r;
}

// ============================================================
extern "C" void kernel_launch(void* const* d_in, const int* in_sizes, int n_in,
                              void* d_out, int out_size) {
    const float* h   = nullptr;
    const float* Wm  = nullptr;
    const float* av  = nullptr;
    const int*   adj = nullptr;
    for (int i = 0; i < n_in; i++) {
        switch (in_sizes[i]) {
            case BB * NN * FIN: h  = (const float*)d_in[i]; break;
            case FO * FIN:      Wm = (const float*)d_in[i]; break;
            case 2 * FO:        av = (const float*)d_in[i]; break;
            default:
                if (in_sizes[i] == (int)((size_t)BB * NN * NN))
                    adj = (const int*)d_in[i];
                break;
        }
    }
    float* out = (float*)d_out;

    cudaFuncSetAttribute(kernelC, cudaFuncAttributeMaxDynamicSharedMemorySize,
                         DSMEM_BYTES);

    kernelA<<<256, 128>>>(h, Wm, av);
    kernelB<<<BB, 256>>>();
    kernelA2<<<dim3(NN / 64, BB), 256>>>();
    kernelC<<<dim3(2, NN / 128, BB), 256, DSMEM_BYTES>>>(adj);
    kernelD<<<BB * NN * FO / 4 / 256, 256>>>(out);
}